// round 1
// baseline (speedup 1.0000x reference)
#include <cuda_runtime.h>

#define RES 128
#define IMG 480
#define NBATCH 16

// out[b, 0, ix, iy, iz] = 1 - RES * tdf
// tdf = min(|zc - d|, 1/RES) if in frustum else 1/RES
// zc = cam_dist - c[iz]; u = fl*c[ix]/zc + (W-1)/2; v = fl*c[iy]/zc + (H-1)/2
// c[i] = (i+0.5)/RES - 0.5

__global__ __launch_bounds__(256)
void backproj_kernel(const float* __restrict__ depth,
                     const float* __restrict__ fl_arr,
                     const float* __restrict__ cd_arr,
                     float* __restrict__ out)
{
    // Each thread handles 4 consecutive iz (float4 store).
    // flat4 index: [b, ix, iy, iz4] where iz4 in [0,32)
    unsigned idx = blockIdx.x * blockDim.x + threadIdx.x;
    // total threads = 16 * 128 * 128 * 32 = 8388608
    unsigned iz4 = idx & 31u;          // 32 groups of 4 z
    unsigned iy  = (idx >> 5) & 127u;
    unsigned ix  = (idx >> 12) & 127u;
    unsigned b   = idx >> 19;          // 0..15

    const float inv_res = 1.0f / (float)RES;
    const float trunc   = inv_res;

    float fl = fl_arr[b];
    float cd = cd_arr[b];

    float cx = ((float)ix + 0.5f) * inv_res - 0.5f;
    float cy = ((float)iy + 0.5f) * inv_res - 0.5f;

    float flx = fl * cx;
    float fly = fl * cy;

    const float uoff = (IMG - 1) * 0.5f;

    const float* dslice = depth + (size_t)b * (IMG * IMG);

    float4 res4;
    float* resp = &res4.x;

    int iz_base = (int)iz4 * 4;
    #pragma unroll
    for (int k = 0; k < 4; k++) {
        int iz = iz_base + k;
        float cz = ((float)iz + 0.5f) * inv_res - 0.5f;
        float zc = cd - cz;
        float inv_zc = 1.0f / zc;
        float u = flx * inv_zc + uoff;
        float v = fly * inv_zc + uoff;

        // round half-to-even like jnp.round, then clip
        float ur = rintf(u);
        float vr = rintf(v);
        int ui = (int)ur;
        int vi = (int)vr;
        ui = min(max(ui, 0), IMG - 1);
        vi = min(max(vi, 0), IMG - 1);

        float d = __ldg(&dslice[vi * IMG + ui]);

        bool in_f = (u >= 0.0f) & (u <= (float)(IMG - 1)) &
                    (v >= 0.0f) & (v <= (float)(IMG - 1)) &
                    (d > 0.0f) & (zc > 0.0f);

        float tdf = fminf(fabsf(zc - d), trunc);
        tdf = in_f ? tdf : trunc;
        resp[k] = 1.0f - (float)RES * tdf;
    }

    // out flat index: b*RES^3 + ix*RES^2 + iy*RES + iz
    size_t o = (((size_t)b * RES + ix) * RES + iy) * RES + iz_base;
    *reinterpret_cast<float4*>(out + o) = res4;
}

extern "C" void kernel_launch(void* const* d_in, const int* in_sizes, int n_in,
                              void* d_out, int out_size)
{
    const float* depth = (const float*)d_in[0];
    const float* fl    = (const float*)d_in[1];
    const float* cd    = (const float*)d_in[2];
    float* out = (float*)d_out;

    // total voxels = 16*128^3 = 33554432 ; /4 per thread = 8388608 threads
    const unsigned total_threads = NBATCH * RES * RES * (RES / 4);
    const unsigned block = 256;
    const unsigned grid = total_threads / block;
    backproj_kernel<<<grid, block>>>(depth, fl, cd, out);
}

// round 2
// speedup vs baseline: 1.2453x; 1.2453x over previous
#include <cuda_runtime.h>

#define RES 128
#define IMG 480
#define NBATCH 16

// Block = (b, ix). 256 threads: tid&31 -> iz group (4 consecutive iz),
// tid>>5 -> iy0, loop iy += 8 (16 iterations).
// Per-iz quantities (zc, 1/zc, ui, u-validity) hoisted to prologue.
// out[b,0,ix,iy,iz] = ok ? 1 - 128*min(|zc-d|, 1/128) : 0   (1-128*trunc == 0)

__global__ __launch_bounds__(256)
void backproj_kernel(const float* __restrict__ depth,
                     const float* __restrict__ fl_arr,
                     const float* __restrict__ cd_arr,
                     float* __restrict__ out)
{
    const int bix = blockIdx.x;      // 0 .. 16*128-1
    const int b   = bix >> 7;
    const int ix  = bix & 127;
    const int tid = threadIdx.x;
    const int iz4 = tid & 31;        // iz base = 4*iz4
    const int iy0 = tid >> 5;        // 0..7

    const float inv_res = 1.0f / (float)RES;
    const float uoff = (IMG - 1) * 0.5f;   // 239.5
    const float wmax = (float)(IMG - 1);   // 479.0
    const float trunc = inv_res;           // 1/128

    const float fl = __ldg(fl_arr + b);
    const float cd = __ldg(cd_arr + b);

    const float cx  = ((float)ix + 0.5f) * inv_res - 0.5f;
    const float flx = fl * cx;

    float zc[4], izc[4];
    int   ui[4];
    bool  uok[4];
    #pragma unroll
    for (int k = 0; k < 4; k++) {
        int iz = iz4 * 4 + k;
        float cz = ((float)iz + 0.5f) * inv_res - 0.5f;
        zc[k]  = cd - cz;
        izc[k] = 1.0f / zc[k];
        float u = flx * izc[k] + uoff;
        ui[k]  = __float2int_rn(u);
        uok[k] = (u >= 0.0f) & (u <= wmax) & (zc[k] > 0.0f);
    }

    const float* __restrict__ ds = depth + (size_t)b * (IMG * IMG);
    float* __restrict__ ob = out + ((size_t)(b * RES + ix)) * (RES * RES) + iz4 * 4;

    float fly  = fl * (((float)iy0 + 0.5f) * inv_res - 0.5f);
    const float dfly = fl * (8.0f * inv_res);

    #pragma unroll 4
    for (int iy = iy0; iy < RES; iy += 8, fly += dfly) {
        float4 r;
        float* rp = &r.x;
        #pragma unroll
        for (int k = 0; k < 4; k++) {
            float v = fly * izc[k] + uoff;
            bool ok = uok[k] & (v >= 0.0f) & (v <= wmax);
            float d = 0.0f;
            if (ok) d = __ldg(ds + __float2int_rn(v) * IMG + ui[k]);
            float val = fmaf(-(float)RES, fminf(fabsf(zc[k] - d), trunc), 1.0f);
            rp[k] = (ok & (d > 0.0f)) ? val : 0.0f;
        }
        *reinterpret_cast<float4*>(ob + iy * RES) = r;
    }
}

extern "C" void kernel_launch(void* const* d_in, const int* in_sizes, int n_in,
                              void* d_out, int out_size)
{
    const float* depth = (const float*)d_in[0];
    const float* fl    = (const float*)d_in[1];
    const float* cd    = (const float*)d_in[2];
    float* out = (float*)d_out;

    const unsigned grid = NBATCH * RES;   // block per (b, ix)
    backproj_kernel<<<grid, 256>>>(depth, fl, cd, out);
}

// round 3
// speedup vs baseline: 1.4058x; 1.1289x over previous
#include <cuda_runtime.h>

#define RES 128
#define IMG 480
#define NBATCH 16

// Block tile: fixed b; ix in [ixo*32, +32), iz in [izo*32, +32), iy in [iyo*16, +16).
// Compute phase: lanes span ix (warp-gather: vi uniform, ui spans ~2 lines).
//   Each warp owns 4 iz values (izl = w + 8k). Per-thread prologue: 4x (zc, 1/zc, ui, uok).
// Store phase: transpose via padded smem tile, lanes span iz -> coalesced 128B rows.
// out[b,0,ix,iy,iz] = ok ? 1 - 128*min(|zc-d|,1/128) : 0   (1 - 128*trunc == 0)

__global__ __launch_bounds__(256)
void backproj_kernel(const float* __restrict__ depth,
                     const float* __restrict__ fl_arr,
                     const float* __restrict__ cd_arr,
                     float* __restrict__ out)
{
    __shared__ float tile[2][32 * 33];

    const int bid = blockIdx.x;          // 16*8*4*4 = 2048 blocks
    const int izo = bid & 3;
    const int ixo = (bid >> 2) & 3;
    const int iyo = (bid >> 4) & 7;
    const int b   = bid >> 7;

    const int tid  = threadIdx.x;
    const int lane = tid & 31;
    const int w    = tid >> 5;           // 0..7

    const float inv_res = 1.0f / (float)RES;
    const float off   = (IMG - 1) * 0.5f;   // 239.5
    const float wmax  = (float)(IMG - 1);   // 479
    const float trunc = inv_res;

    const float fl = __ldg(fl_arr + b);
    const float cd = __ldg(cd_arr + b);

    const int ix = ixo * 32 + lane;
    const float flx = fl * (((float)ix + 0.5f) * inv_res - 0.5f);

    // per-thread iz values: izl[k] = w + 8k  (warp-uniform)
    float zc[4], izc[4];
    int   ui[4], izl[4];
    bool  uok[4];
    #pragma unroll
    for (int k = 0; k < 4; k++) {
        izl[k] = w + 8 * k;
        int iz = izo * 32 + izl[k];
        float cz = ((float)iz + 0.5f) * inv_res - 0.5f;
        zc[k]  = cd - cz;
        izc[k] = 1.0f / zc[k];
        float u = flx * izc[k] + off;
        ui[k]  = __float2int_rn(u);
        uok[k] = (u >= 0.0f) & (u <= wmax) & (zc[k] > 0.0f);
    }

    const float* __restrict__ ds = depth + (size_t)b * (IMG * IMG);

    // store-phase constants: thread stores rows r = w*4+q (ix_local), cols = lane (iz_local)
    // out[((b*128 + ixo*32 + r)*128 + iy)*128 + izo*32 + lane]
    const size_t obase = ((size_t)b * RES + ixo * 32) * (RES * RES)
                       + (size_t)izo * 32 + lane;

    const int iy0 = iyo * 16;

    #pragma unroll 2
    for (int j = 0; j < 16; j++) {
        const int iy = iy0 + j;
        const int buf = j & 1;
        const float fly = fl * (((float)iy + 0.5f) * inv_res - 0.5f);

        // compute 4 voxels (lane=ix, izl[k])
        #pragma unroll
        for (int k = 0; k < 4; k++) {
            float v = fly * izc[k] + off;
            bool ok = uok[k] & (v >= 0.0f) & (v <= wmax);
            float d = 0.0f;
            if (ok) d = __ldg(ds + __float2int_rn(v) * IMG + ui[k]);
            float val = fmaf(-(float)RES, fminf(fabsf(zc[k] - d), trunc), 1.0f);
            tile[buf][lane * 33 + izl[k]] = (ok & (d > 0.0f)) ? val : 0.0f;
        }

        __syncthreads();

        // store phase: 4 rows per thread, lanes span iz (coalesced 128B per row)
        const size_t oy = obase + (size_t)iy * RES;
        #pragma unroll
        for (int q = 0; q < 4; q++) {
            int r = w * 4 + q;
            out[oy + (size_t)r * (RES * RES)] = tile[buf][r * 33 + lane];
        }
        // no second barrier: double buffer + next iter's barrier orders reuse
    }
}

extern "C" void kernel_launch(void* const* d_in, const int* in_sizes, int n_in,
                              void* d_out, int out_size)
{
    const float* depth = (const float*)d_in[0];
    const float* fl    = (const float*)d_in[1];
    const float* cd    = (const float*)d_in[2];
    float* out = (float*)d_out;

    const unsigned grid = NBATCH * 8 * 4 * 4;   // 2048 blocks
    backproj_kernel<<<grid, 256>>>(depth, fl, cd, out);
}